// round 10
// baseline (speedup 1.0000x reference)
#include <cuda_runtime.h>
#include <cstdint>

// Quantizer: per-row symmetric int4 quant + nibble pack. x: [8192, 4096] fp32.
// Output = concat(packed, scales) upcast to fp32:
//   out[0 .. N*2048)       fp32 value of each packed signed byte
//   out[N*2048 .. +N)      fp32 per-row scale (absmax / 7)
//
// R9: 512-thread CTA processing 2 rows, SAME 16 floats/thread (31 regs) as the
// best 256T/1-row kernel — tests barrier amortization WITHOUT the occupancy
// loss that sank R6 (which doubled regs/thread). Warps 0-7 = row A,
// warps 8-15 = row B; one __syncthreads pair per 2 rows.

#define H 4096
#define HP (H / 2)
#define THREADS 512

__device__ __forceinline__ float pack2(float a, float b, float inv) {
    int q0 = min(max(__float2int_rn(a * inv), -8), 7);
    int q1 = min(max(__float2int_rn(b * inv), -8), 7);
    return (float)((int8_t)(((q1 & 0xF) << 4) | (q0 & 0xF)));
}

__device__ __forceinline__ float amax4(float4 v) {
    return fmaxf(fmaxf(fabsf(v.x), fabsf(v.y)), fmaxf(fabsf(v.z), fabsf(v.w)));
}

__global__ __launch_bounds__(THREADS, 4)
void quant_pack_kernel(const float* __restrict__ x,
                       float* __restrict__ out_packed,
                       float* __restrict__ out_scales)
{
    const int t = threadIdx.x;
    const int half = t >> 8;            // 0 = row A (warps 0-7), 1 = row B
    const int u = t & 255;              // thread index within the row's 256
    const int row = blockIdx.x * 2 + half;

    const float4* __restrict__ xrow =
        reinterpret_cast<const float4*>(x + (size_t)row * H);

    // 4 front-batched LDG.128 per thread; paired mapping for float4 stores.
    float4 v0 = xrow[2 * u];
    float4 v1 = xrow[2 * u + 1];
    float4 v2 = xrow[512 + 2 * u];
    float4 v3 = xrow[512 + 2 * u + 1];

    float m = fmaxf(fmaxf(amax4(v0), amax4(v1)), fmaxf(amax4(v2), amax4(v3)));

    // Warp absmax.
#pragma unroll
    for (int o = 16; o > 0; o >>= 1)
        m = fmaxf(m, __shfl_xor_sync(0xffffffffu, m, o));

    __shared__ float warpmax[THREADS / 32];     // [0..7]=row A, [8..15]=row B
    __shared__ float s_inv[2];
    const int wid = t >> 5;
    const int lane = t & 31;
    if (lane == 0) warpmax[wid] = m;
    __syncthreads();

    // Warp 0 finalizes row A, warp 1 finalizes row B — in parallel.
    if (wid < 2) {
        float mm = (lane < 8) ? warpmax[wid * 8 + lane] : 0.0f;
#pragma unroll
        for (int o = 4; o > 0; o >>= 1)
            mm = fmaxf(mm, __shfl_xor_sync(0xffffffffu, mm, o));
        if (lane == 0) {
            const float sc = mm / 7.0f;              // exact divide, per row
            out_scales[blockIdx.x * 2 + wid] = sc;
            s_inv[wid] = 1.0f / sc;                  // exact reciprocal
        }
    }
    __syncthreads();
    const float inv = s_inv[half];

    // Two STG.128 streaming stores per thread.
    float4* __restrict__ orow =
        reinterpret_cast<float4*>(out_packed + (size_t)row * HP);
    float4 o0, o1;
    o0.x = pack2(v0.x, v0.y, inv);
    o0.y = pack2(v0.z, v0.w, inv);
    o0.z = pack2(v1.x, v1.y, inv);
    o0.w = pack2(v1.z, v1.w, inv);
    o1.x = pack2(v2.x, v2.y, inv);
    o1.y = pack2(v2.z, v2.w, inv);
    o1.z = pack2(v3.x, v3.y, inv);
    o1.w = pack2(v3.z, v3.w, inv);
    __stcs(&orow[u], o0);
    __stcs(&orow[256 + u], o1);
}

extern "C" void kernel_launch(void* const* d_in, const int* in_sizes, int n_in,
                              void* d_out, int out_size)
{
    const float* x = (const float*)d_in[0];
    const int N = in_sizes[0] / H;                   // 8192 rows

    float* out_packed = (float*)d_out;
    float* out_scales = (float*)d_out + (size_t)N * HP;

    quant_pack_kernel<<<N / 2, THREADS>>>(x, out_packed, out_scales);
}

// round 11
// speedup vs baseline: 1.0049x; 1.0049x over previous
#include <cuda_runtime.h>
#include <cstdint>

// Quantizer: per-row symmetric int4 quant + nibble pack. x: [8192, 4096] fp32.
// Output = concat(packed, scales) upcast to fp32:
//   out[0 .. N*2048)       fp32 value of each packed signed byte
//   out[N*2048 .. +N)      fp32 per-row scale (absmax / 7)
//
// FINAL (converged): best-measured variant (R5) — 1 row/CTA, 256T, paired
// input mapping -> 2x STG.128, streaming hints, warp-shuffle reduce.
// kernel 26.78us / bench 32.83us. Measured DRAM traffic (~160MB) over achieved
// BW (~6TB/s) == kernel time: at the mixed-stream HBM ceiling. Structural
// alternatives (row fusion, wider CTAs, write-through, default caching) all
// measured neutral or worse (R6/R7/R9).

#define H 4096
#define HP (H / 2)
#define THREADS 256
// thread t owns input float4s {2t, 2t+1, 512+2t, 512+2t+1} (16 floats),
// emitting output float4s {t, 256+t} (8 packed-byte floats).

__device__ __forceinline__ float pack2(float a, float b, float inv) {
    int q0 = min(max(__float2int_rn(a * inv), -8), 7);
    int q1 = min(max(__float2int_rn(b * inv), -8), 7);
    return (float)((int8_t)(((q1 & 0xF) << 4) | (q0 & 0xF)));
}

__global__ __launch_bounds__(THREADS, 8)
void quant_pack_kernel(const float* __restrict__ x,
                       float* __restrict__ out_packed,
                       float* __restrict__ out_scales)
{
    const int t = threadIdx.x;
    const int row = blockIdx.x;
    const float4* __restrict__ xrow =
        reinterpret_cast<const float4*>(x + (size_t)row * H);

    // Streaming loads; keep all 16 floats in registers.
    float4 v0 = __ldcs(&xrow[2 * t]);
    float4 v1 = __ldcs(&xrow[2 * t + 1]);
    float4 v2 = __ldcs(&xrow[512 + 2 * t]);
    float4 v3 = __ldcs(&xrow[512 + 2 * t + 1]);

    float m = fmaxf(fmaxf(fabsf(v0.x), fabsf(v0.y)), fmaxf(fabsf(v0.z), fabsf(v0.w)));
    m = fmaxf(m, fmaxf(fmaxf(fabsf(v1.x), fabsf(v1.y)), fmaxf(fabsf(v1.z), fabsf(v1.w))));
    m = fmaxf(m, fmaxf(fmaxf(fabsf(v2.x), fabsf(v2.y)), fmaxf(fabsf(v2.z), fabsf(v2.w))));
    m = fmaxf(m, fmaxf(fmaxf(fabsf(v3.x), fabsf(v3.y)), fmaxf(fabsf(v3.z), fabsf(v3.w))));

    // Warp absmax, then cross-warp via shared + warp-0 shuffle reduce.
#pragma unroll
    for (int o = 16; o > 0; o >>= 1)
        m = fmaxf(m, __shfl_xor_sync(0xffffffffu, m, o));

    __shared__ float warpmax[THREADS / 32];
    __shared__ float s_inv;
    if ((t & 31) == 0) warpmax[t >> 5] = m;
    __syncthreads();
    if (t < 32) {
        float mm = (t < THREADS / 32) ? warpmax[t] : 0.0f;
#pragma unroll
        for (int o = 4; o > 0; o >>= 1)
            mm = fmaxf(mm, __shfl_xor_sync(0xffffffffu, mm, o));
        if (t == 0) {
            const float sc = mm / 7.0f;   // exact divide, once per row
            out_scales[row] = sc;
            s_inv = 1.0f / sc;            // exact reciprocal, once per row
        }
    }
    __syncthreads();
    const float inv = s_inv;

    // Two float4 (STG.128) streaming stores per thread.
    float4* __restrict__ orow =
        reinterpret_cast<float4*>(out_packed + (size_t)row * HP);
    float4 o0, o1;
    o0.x = pack2(v0.x, v0.y, inv);
    o0.y = pack2(v0.z, v0.w, inv);
    o0.z = pack2(v1.x, v1.y, inv);
    o0.w = pack2(v1.z, v1.w, inv);
    o1.x = pack2(v2.x, v2.y, inv);
    o1.y = pack2(v2.z, v2.w, inv);
    o1.z = pack2(v3.x, v3.y, inv);
    o1.w = pack2(v3.z, v3.w, inv);
    __stcs(&orow[t], o0);
    __stcs(&orow[256 + t], o1);
}

extern "C" void kernel_launch(void* const* d_in, const int* in_sizes, int n_in,
                              void* d_out, int out_size)
{
    const float* x = (const float*)d_in[0];
    const int N = in_sizes[0] / H;                   // 8192 rows

    float* out_packed = (float*)d_out;
    float* out_scales = (float*)d_out + (size_t)N * HP;

    quant_pack_kernel<<<N, THREADS>>>(x, out_packed, out_scales);
}

// round 13
// speedup vs baseline: 1.0059x; 1.0010x over previous
#include <cuda_runtime.h>
#include <cstdint>

// Quantizer: per-row symmetric int4 quant + nibble pack. x: [8192, 4096] fp32.
// Output = concat(packed, scales) upcast to fp32:
//   out[0 .. N*2048)       fp32 value of each packed signed byte
//   out[N*2048 .. +N)      fp32 per-row scale (absmax / 7)
//
// (Resubmission: Round-12 bench was an infra failure — container never ran it.)
// R11: best structure (R5/R10: 1 row/CTA, 256T, paired mapping, 2x STG.128,
// streaming hints) + pure-FP pack path: rintf/fminf/fmaxf round+clamp and
// direct float synthesis of the signed packed-byte value
//   byte = 16*q_hi + (q_lo < 0 ? q_lo + 16 : q_lo)
// (all values exactly representable -> bit-identical to the int path) —
// removes F2I/IMNMX/LOP/I2F per element, moving work to the idle FMA pipe.

#define H 4096
#define HP (H / 2)
#define THREADS 256
// thread t owns input float4s {2t, 2t+1, 512+2t, 512+2t+1} (16 floats),
// emitting output float4s {t, 256+t} (8 packed-byte floats).

__device__ __forceinline__ float qclamp(float v, float inv) {
    // round-to-nearest-even then clip to [-8, 7]; exact small-int fp32 math
    return fmaxf(fminf(rintf(v * inv), 7.0f), -8.0f);
}

__device__ __forceinline__ float pack2(float a, float b, float inv) {
    const float q0 = qclamp(a, inv);                 // low nibble (even col)
    const float q1 = qclamp(b, inv);                 // high nibble (odd col)
    const float lo = (q0 < 0.0f) ? q0 + 16.0f : q0;  // q0 & 0xF as a value
    return fmaf(q1, 16.0f, lo);                      // signed byte value
}

__device__ __forceinline__ float amax4(float4 v) {
    return fmaxf(fmaxf(fabsf(v.x), fabsf(v.y)), fmaxf(fabsf(v.z), fabsf(v.w)));
}

__global__ __launch_bounds__(THREADS, 8)
void quant_pack_kernel(const float* __restrict__ x,
                       float* __restrict__ out_packed,
                       float* __restrict__ out_scales)
{
    const int t = threadIdx.x;
    const int row = blockIdx.x;
    const float4* __restrict__ xrow =
        reinterpret_cast<const float4*>(x + (size_t)row * H);

    // Streaming loads; keep all 16 floats in registers.
    float4 v0 = __ldcs(&xrow[2 * t]);
    float4 v1 = __ldcs(&xrow[2 * t + 1]);
    float4 v2 = __ldcs(&xrow[512 + 2 * t]);
    float4 v3 = __ldcs(&xrow[512 + 2 * t + 1]);

    float m = fmaxf(fmaxf(amax4(v0), amax4(v1)), fmaxf(amax4(v2), amax4(v3)));

    // Warp absmax, then cross-warp via shared + warp-0 shuffle reduce.
#pragma unroll
    for (int o = 16; o > 0; o >>= 1)
        m = fmaxf(m, __shfl_xor_sync(0xffffffffu, m, o));

    __shared__ float warpmax[THREADS / 32];
    __shared__ float s_inv;
    if ((t & 31) == 0) warpmax[t >> 5] = m;
    __syncthreads();
    if (t < 32) {
        float mm = (t < THREADS / 32) ? warpmax[t] : 0.0f;
#pragma unroll
        for (int o = 4; o > 0; o >>= 1)
            mm = fmaxf(mm, __shfl_xor_sync(0xffffffffu, mm, o));
        if (t == 0) {
            const float sc = mm / 7.0f;   // exact divide, once per row
            out_scales[row] = sc;
            s_inv = 1.0f / sc;            // exact reciprocal, once per row
        }
    }
    __syncthreads();
    const float inv = s_inv;

    // Two float4 (STG.128) streaming stores per thread.
    float4* __restrict__ orow =
        reinterpret_cast<float4*>(out_packed + (size_t)row * HP);
    float4 o0, o1;
    o0.x = pack2(v0.x, v0.y, inv);
    o0.y = pack2(v0.z, v0.w, inv);
    o0.z = pack2(v1.x, v1.y, inv);
    o0.w = pack2(v1.z, v1.w, inv);
    o1.x = pack2(v2.x, v2.y, inv);
    o1.y = pack2(v2.z, v2.w, inv);
    o1.z = pack2(v3.x, v3.y, inv);
    o1.w = pack2(v3.z, v3.w, inv);
    __stcs(&orow[t], o0);
    __stcs(&orow[256 + t], o1);
}

extern "C" void kernel_launch(void* const* d_in, const int* in_sizes, int n_in,
                              void* d_out, int out_size)
{
    const float* x = (const float*)d_in[0];
    const int N = in_sizes[0] / H;                   // 8192 rows

    float* out_packed = (float*)d_out;
    float* out_scales = (float*)d_out + (size_t)N * HP;

    quant_pack_kernel<<<N, THREADS>>>(x, out_packed, out_scales);
}